// round 12
// baseline (speedup 1.0000x reference)
#include <cuda_runtime.h>
#include <cuda_bf16.h>

#define HW 4096
typedef unsigned int u32;

// ---------------- scratch (no allocs allowed) ----------------
__device__ __align__(16) float g_xt[4 * 64 * 64 * 64];          // channels-last x
// fragment-order W images: per tap 2048 u32 (hi) + 2048 u32 (lo)
__device__ __align__(16) unsigned short g_wfh[83 * 4096];
__device__ __align__(16) unsigned short g_wfl[83 * 4096];
__device__ int   g_q;
__device__ int   g_cnt[256];
__device__ float g_p3[4 * 128 * 64 * 128];                      // conv3 partials
__device__ float g_p2[2 * 128 * 64 * 128];                      // conv2 partials

// ---------------------------------------------------------------------------
__global__ void prep_kernel(const float* __restrict__ x,
                            const float* __restrict__ f1,
                            const float* __restrict__ f2,
                            const float* __restrict__ f3) {
    int blk = blockIdx.x;
    if (blk < 256) {
        __shared__ float t[64][65];
        int b = blk >> 6, h = blk & 63;
        for (int i = threadIdx.x; i < 4096; i += 256) {
            int c = i >> 6, w = i & 63;
            t[w][c] = x[((b * 64 + c) * 64 + h) * 64 + w];
        }
        __syncthreads();
        for (int i = threadIdx.x; i < 4096; i += 256) {
            int w = i >> 6, c = i & 63;
            g_xt[((b * 64 + h) * 64 + w) * 64 + c] = t[w][c];
        }
    } else if (blk == 256) {
        if (threadIdx.x < 256) g_cnt[threadIdx.x] = 0;
        if (threadIdx.x == 0) g_q = 0;
    } else {
        int idx = (blk - 257) * 256 + threadIdx.x;
        if (idx < 339968) {
            const float* w; int K, t0, local;
            if (idx < 36864)       { w = f1; K = 9;  t0 = 0;  local = idx; }
            else if (idx < 139264) { w = f2; K = 25; t0 = 9;  local = idx - 36864; }
            else                   { w = f3; K = 49; t0 = 34; local = idx - 139264; }
            int k  = local % K;
            int c  = (local / K) & 63;
            int co = local / (K * 64);
            float v = w[local];
            __nv_bfloat16 h = __float2bfloat16(v);
            float hf = __bfloat162float(h);
            __nv_bfloat16 l = __float2bfloat16(v - hf);
            // fragment-order address: mma m16n8k16 B frag via ldmatrix-equivalent map
            int nb = co >> 4;                       // 16-co block
            int k4 = c >> 4;                        // 16-ch (k16) block
            int j  = ((co >> 3) & 1) * 2 + ((c >> 3) & 1);   // reg within uint4
            int ln = ((co & 7) << 2) | ((c & 7) >> 1);       // lane
            int slot = (t0 + k) * 2048 + ((nb * 4 + k4) * 32 + ln) * 4 + j;
            int ui = slot * 2 + (c & 1);
            g_wfh[ui] = __bfloat16_as_ushort(h);
            g_wfl[ui] = __bfloat16_as_ushort(l);
        }
    }
}

// ---------------- mma helpers (target-portable: sm_80 features) -------------
#define LDSM4(r, a) \
    asm volatile("ldmatrix.sync.aligned.m8n8.x4.shared.b16 {%0,%1,%2,%3}, [%4];" \
        : "=r"((r)[0]), "=r"((r)[1]), "=r"((r)[2]), "=r"((r)[3]) : "r"(a))

#define MMA16(d, a, b0, b1) \
    asm volatile("mma.sync.aligned.m16n8k16.row.col.f32.bf16.bf16.f32 " \
        "{%0,%1,%2,%3},{%4,%5,%6,%7},{%8,%9},{%0,%1,%2,%3};" \
        : "+f"((d)[0]), "+f"((d)[1]), "+f"((d)[2]), "+f"((d)[3]) \
        : "r"((a)[0]), "r"((a)[1]), "r"((a)[2]), "r"((a)[3]), "r"(b0), "r"(b1))

__device__ __forceinline__ u32 smem_u32(const void* p) {
    u32 a;
    asm("{ .reg .u64 t; cvta.to.shared.u64 t, %1; cvt.u32.u64 %0, t; }" : "=r"(a) : "l"(p));
    return a;
}

struct Bil { float w00, w01, w10, w11; u32 pk0, pk1; };

// ---------------------------------------------------------------------------
// Persistent DCNv2, 256 thr (8 warps, 32px x 32co), S single-buffer 32KB only,
// B-fragments loaded directly from global (fragment-order, L1/L2-hit).
// ---------------------------------------------------------------------------
#define N_ITEMS 896
#define CTRL 32768
#define SMEM_BYTES 32896

__global__ void __launch_bounds__(256, 2)
dcn_kernel(const float* __restrict__ off1, const float* __restrict__ m1,
           const float* __restrict__ off2, const float* __restrict__ m2,
           const float* __restrict__ off3, const float* __restrict__ m3,
           float* __restrict__ out)
{
    extern __shared__ char smem[];
    const u32 sb = smem_u32(smem);
    const int tid  = threadIdx.x;
    const int lane = tid & 31;
    const int wid  = tid >> 5;
    int* s_item = (int*)(smem + CTRL);
    int* s_last = (int*)(smem + CTRL + 4);

    const int hw_id = tid >> 4, m = tid & 15;
    const int wpx = wid & 3, wco = wid >> 2;
    const int rowA  = lane & 15;
    const int acol0 = (lane >> 4) << 4;
    const int aswz  = (rowA & 7) << 4;
    const int rbA0  = (32 * wpx + rowA) * 128;
    const int rbA1  = rbA0 + 16 * 128;
    const int r4 = lane >> 2, c2 = 2 * (lane & 3);

    for (;;) {
        __syncthreads();
        if (tid == 0) *s_item = atomicAdd(&g_q, 1);
        __syncthreads();
        int item = *s_item;
        if (item >= N_ITEMS) return;

        int K, kw, pad, co0, wt0, chunk, k0, klen, seg, nsegs, cidx;
        const float *off, *msk;
        float* pbase = 0;
        if (item < 512) {
            chunk = item >> 2; seg = item & 3;
            K = 49; kw = 7; pad = 3; co0 = 128; wt0 = 34;
            k0 = (seg == 0) ? 0 : (13 + 12 * (seg - 1));
            klen = (seg == 0) ? 13 : 12;
            nsegs = 4; cidx = chunk;
            off = off3; msk = m3;
            pbase = g_p3 + ((size_t)(seg * 128 + chunk)) * (64 * 128);
        } else if (item < 768) {
            int it = item - 512;
            chunk = it >> 1; seg = it & 1;
            K = 25; kw = 5; pad = 2; co0 = 64; wt0 = 9;
            k0 = (seg == 0) ? 0 : 13;
            klen = (seg == 0) ? 13 : 12;
            nsegs = 2; cidx = 128 + chunk;
            off = off2; msk = m2;
            pbase = g_p2 + ((size_t)(seg * 128 + chunk)) * (64 * 128);
        } else {
            chunk = item - 768; seg = 0;
            K = 9; kw = 3; pad = 1; co0 = 0; wt0 = 0;
            k0 = 0; klen = 9; nsegs = 1; cidx = 0;
            off = off1; msk = m1;
        }

        const int chunkPx0 = chunk << 7;
        const int b = chunkPx0 >> 12;
        const float* xtB = g_xt + (size_t)b * (64 * 64 * 64);
        const int pixl = (chunkPx0 + hw_id * 8 + (m & 7)) & 4095;
        const int xo_own = pixl & 63, yo_own = pixl >> 6;
        const float* offB = off + (size_t)b * 2 * K * HW;
        const float* mskB = msk + (size_t)b * K * HW;
        // per-warp fragment base index within a tap image (uint4 units)
        const int fbase0 = ((wco * 2 + 0) * 4) * 32 + lane;   // p=0
        const int fbase1 = ((wco * 2 + 1) * 4) * 32 + lane;   // p=1

        float acc[2][4][4];
#pragma unroll
        for (int i = 0; i < 2; ++i)
#pragma unroll
            for (int j = 0; j < 4; ++j)
#pragma unroll
                for (int q = 0; q < 4; ++q) acc[i][j][q] = 0.f;

        // ---- prologue: prefetch tap k0 offsets ----
        float pf_dy, pf_dx, pf_mm;
        {
            const float* offY = offB + (size_t)(2 * k0) * HW;
            pf_dy = __ldg(offY + pixl);
            pf_dx = __ldg(offY + HW + pixl);
            pf_mm = __ldg(mskB + (size_t)k0 * HW + pixl);
        }

        for (int t = 0; t < klen; ++t) {
            const int k = k0 + t;
            const bool more = (t + 1 < klen);
            __syncthreads();   // all warps done with GEMM(t-1): S reusable

            // ---- Bil for tap t from prefetched regs ----
            Bil bl;
            {
                const int ky = k / kw, kx = k - ky * kw;
                float py  = (float)(yo_own - pad + ky) + pf_dy;
                float pxx = (float)(xo_own - pad + kx) + pf_dx;
                float mm  = pf_mm;
                float fy = floorf(py), fx = floorf(pxx);
                float wy = py - fy,    wx = pxx - fx;
                int y0 = (int)fy, x0 = (int)fx;
                int y1 = y0 + 1,  x1 = x0 + 1;
                float vy0 = (y0 >= 0 && y0 < 64) ? 1.f : 0.f;
                float vy1 = (y1 >= 0 && y1 < 64) ? 1.f : 0.f;
                float vx0 = (x0 >= 0 && x0 < 64) ? 1.f : 0.f;
                float vx1 = (x1 >= 0 && x1 < 64) ? 1.f : 0.f;
                bl.w00 = (1.f - wy) * (1.f - wx) * mm * vy0 * vx0;
                bl.w01 = (1.f - wy) * wx         * mm * vy0 * vx1;
                bl.w10 = wy         * (1.f - wx) * mm * vy1 * vx0;
                bl.w11 = wy         * wx         * mm * vy1 * vx1;
                int cy0 = min(max(y0, 0), 63), cy1 = min(max(y1, 0), 63);
                int cx0 = min(max(x0, 0), 63), cx1 = min(max(x1, 0), 63);
                bl.pk0 = ((u32)(cy0 * 64 + cx0) << 16) | (u32)(cy0 * 64 + cx1);
                bl.pk1 = ((u32)(cy1 * 64 + cx0) << 16) | (u32)(cy1 * 64 + cx1);
            }

            // ---- prefetch offsets for tap t+1 ----
            if (more) {
                const float* offY = offB + (size_t)(2 * (k + 1)) * HW;
                pf_dy = __ldg(offY + pixl);
                pf_dx = __ldg(offY + HW + pixl);
                pf_mm = __ldg(mskB + (size_t)(k + 1) * HW + pixl);
            }

            // ---- gather tap t -> S (bf16 hi/lo) ----
            {
                const float4* vp = (const float4*)xtB;
                const int sbase = lane & 16;
#pragma unroll 4
                for (int it = 0; it < 8; ++it) {
                    int src = sbase + it;
                    float W00 = __shfl_sync(0xffffffffu, bl.w00, src);
                    float W01 = __shfl_sync(0xffffffffu, bl.w01, src);
                    float W10 = __shfl_sync(0xffffffffu, bl.w10, src);
                    float W11 = __shfl_sync(0xffffffffu, bl.w11, src);
                    u32 P0 = __shfl_sync(0xffffffffu, bl.pk0, src);
                    u32 P1 = __shfl_sync(0xffffffffu, bl.pk1, src);

                    float4 v00 = vp[(P0 >> 16) * 16 + m];
                    float4 v01 = vp[(P0 & 0xffffu) * 16 + m];
                    float4 v10 = vp[(P1 >> 16) * 16 + m];
                    float4 v11 = vp[(P1 & 0xffffu) * 16 + m];

                    float s0 = fmaf(W00, v00.x, fmaf(W01, v01.x, fmaf(W10, v10.x, W11 * v11.x)));
                    float s1 = fmaf(W00, v00.y, fmaf(W01, v01.y, fmaf(W10, v10.y, W11 * v11.y)));
                    float s2 = fmaf(W00, v00.z, fmaf(W01, v01.z, fmaf(W10, v10.z, W11 * v11.z)));
                    float s3 = fmaf(W00, v00.w, fmaf(W01, v01.w, fmaf(W10, v10.w, W11 * v11.w)));

                    __nv_bfloat162 h01 = __floats2bfloat162_rn(s0, s1);
                    __nv_bfloat162 h23 = __floats2bfloat162_rn(s2, s3);
                    float2 f01 = __bfloat1622float2(h01);
                    float2 f23 = __bfloat1622float2(h23);
                    __nv_bfloat162 l01 = __floats2bfloat162_rn(s0 - f01.x, s1 - f01.y);
                    __nv_bfloat162 l23 = __floats2bfloat162_rn(s2 - f23.x, s3 - f23.y);

                    int px = hw_id * 8 + it;
                    int cb = px * 128 + ((8 * m) ^ ((px & 7) << 4));
                    *(uint2*)(smem + cb)         = make_uint2(*(u32*)&h01, *(u32*)&h23);
                    *(uint2*)(smem + 16384 + cb) = make_uint2(*(u32*)&l01, *(u32*)&l23);
                }
            }
            __syncthreads();   // S visible

            // ---- GEMM(t): B frags straight from global (fragment-order) ----
            const uint4* wfH = (const uint4*)g_wfh + (size_t)(wt0 + k) * 512;
            const uint4* wfL = (const uint4*)g_wfl + (size_t)(wt0 + k) * 512;
#pragma unroll
            for (int k4 = 0; k4 < 4; ++k4) {
                u32 colA = (u32)((32 * k4 + acol0) ^ aswz);
                u32 aH0[4], aH1[4], aL0[4], aL1[4];
                LDSM4(aH0, sb + rbA0 + colA);
                LDSM4(aH1, sb + rbA1 + colA);
                LDSM4(aL0, sb + 16384 + rbA0 + colA);
                LDSM4(aL1, sb + 16384 + rbA1 + colA);
#pragma unroll
                for (int p = 0; p < 2; ++p) {
                    int fidx = (p ? fbase1 : fbase0) + k4 * 32;
                    uint4 bh4 = __ldg(wfH + fidx);
                    uint4 bl4 = __ldg(wfL + fidx);
                    MMA16(acc[0][2 * p],     aH0, bh4.x, bh4.y);
                    MMA16(acc[1][2 * p],     aH1, bh4.x, bh4.y);
                    MMA16(acc[0][2 * p + 1], aH0, bh4.z, bh4.w);
                    MMA16(acc[1][2 * p + 1], aH1, bh4.z, bh4.w);
                    MMA16(acc[0][2 * p],     aL0, bh4.x, bh4.y);
                    MMA16(acc[1][2 * p],     aL1, bh4.x, bh4.y);
                    MMA16(acc[0][2 * p + 1], aL0, bh4.z, bh4.w);
                    MMA16(acc[1][2 * p + 1], aL1, bh4.z, bh4.w);
                    MMA16(acc[0][2 * p],     aH0, bl4.x, bl4.y);
                    MMA16(acc[1][2 * p],     aH1, bl4.x, bl4.y);
                    MMA16(acc[0][2 * p + 1], aH0, bl4.z, bl4.w);
                    MMA16(acc[1][2 * p + 1], aH1, bl4.z, bl4.w);
                }
            }
        }

        // ---------------- epilogue ----------------
        if (nsegs == 1) {
            float* ob = out + (size_t)(b * 192 + co0) * HW;
#pragma unroll
            for (int mt = 0; mt < 2; ++mt) {
                int pxl = 32 * wpx + 16 * mt + r4;
                int pix0 = (chunkPx0 + pxl) & 4095;
                int pix1 = (chunkPx0 + pxl + 8) & 4095;
#pragma unroll
                for (int nt = 0; nt < 4; ++nt) {
                    int co = 32 * wco + 8 * nt + c2;
                    ob[(size_t)co * HW + pix0]       = acc[mt][nt][0];
                    ob[(size_t)(co + 1) * HW + pix0] = acc[mt][nt][1];
                    ob[(size_t)co * HW + pix1]       = acc[mt][nt][2];
                    ob[(size_t)(co + 1) * HW + pix1] = acc[mt][nt][3];
                }
            }
        } else {
#pragma unroll
            for (int mt = 0; mt < 2; ++mt) {
                int pxl = 32 * wpx + 16 * mt + r4;
#pragma unroll
                for (int nt = 0; nt < 4; ++nt) {
                    int co = 32 * wco + 8 * nt + c2;
                    pbase[co * 128 + pxl]           = acc[mt][nt][0];
                    pbase[(co + 1) * 128 + pxl]     = acc[mt][nt][1];
                    pbase[co * 128 + pxl + 8]       = acc[mt][nt][2];
                    pbase[(co + 1) * 128 + pxl + 8] = acc[mt][nt][3];
                }
            }
            __threadfence();
            __syncthreads();
            if (tid == 0)
                *s_last = (atomicAdd(&g_cnt[cidx], 1) == nsegs - 1) ? 1 : 0;
            __syncthreads();
            if (*s_last) {
                const float* basep = (nsegs == 4) ? g_p3 : g_p2;
                int px  = tid & 127;
                int coh = tid >> 7;
                float* outB = out + (size_t)(b * 192 + co0 + coh * 32) * HW
                                  + ((chunkPx0 + px) & 4095);
                for (int co = 0; co < 32; ++co) {
                    int coa = coh * 32 + co;
                    float s = 0.f;
                    for (int sg = 0; sg < nsegs; ++sg)
                        s += basep[((size_t)(sg * 128 + chunk) * 64 + coa) * 128 + px];
                    outB[(size_t)co * HW] = s;
                }
            }
        }
    }
}

extern "C" void kernel_launch(void* const* d_in, const int* in_sizes, int n_in,
                              void* d_out, int out_size) {
    const float* x  = (const float*)d_in[0];
    const float* f1 = (const float*)d_in[1];
    const float* o1 = (const float*)d_in[2];
    const float* m1 = (const float*)d_in[3];
    const float* f2 = (const float*)d_in[4];
    const float* o2 = (const float*)d_in[5];
    const float* m2 = (const float*)d_in[6];
    const float* f3 = (const float*)d_in[7];
    const float* o3 = (const float*)d_in[8];
    const float* m3 = (const float*)d_in[9];
    float* out = (float*)d_out;

    cudaFuncSetAttribute(dcn_kernel, cudaFuncAttributeMaxDynamicSharedMemorySize, SMEM_BYTES);
    prep_kernel<<<1585, 256>>>(x, f1, f2, f3);
    dcn_kernel<<<296, 256, SMEM_BYTES>>>(o1, m1, o2, m2, o3, m3, out);
}

// round 16
// speedup vs baseline: 1.5545x; 1.5545x over previous
#include <cuda_runtime.h>
#include <cuda_bf16.h>

#define HW 4096
typedef unsigned int u32;

// ---------------- scratch (no allocs allowed) ----------------
__device__ __align__(16) float g_xt[4 * 64 * 64 * 64];           // channels-last x
__device__ __align__(16) unsigned short g_whimg[83 * 4096];      // per-tap 8KB swizzled W hi (bf16)
__device__ __align__(16) unsigned short g_wlimg[83 * 4096];      // per-tap 8KB swizzled W lo (bf16)
__device__ int   g_q;
__device__ int   g_cnt[256];
__device__ float g_p3[4 * 128 * 64 * 128];                       // conv3 partials
__device__ float g_p2[2 * 128 * 64 * 128];                       // conv2 partials

// ---------------------------------------------------------------------------
__global__ void prep_kernel(const float* __restrict__ x,
                            const float* __restrict__ f1,
                            const float* __restrict__ f2,
                            const float* __restrict__ f3) {
    int blk = blockIdx.x;
    if (blk < 256) {
        __shared__ float t[64][65];
        int b = blk >> 6, h = blk & 63;
        for (int i = threadIdx.x; i < 4096; i += 256) {
            int c = i >> 6, w = i & 63;
            t[w][c] = x[((b * 64 + c) * 64 + h) * 64 + w];
        }
        __syncthreads();
        for (int i = threadIdx.x; i < 4096; i += 256) {
            int w = i >> 6, c = i & 63;
            g_xt[((b * 64 + h) * 64 + w) * 64 + c] = t[w][c];
        }
    } else if (blk == 256) {
        if (threadIdx.x < 256) g_cnt[threadIdx.x] = 0;
        if (threadIdx.x == 0) g_q = 0;
    } else {
        int idx = (blk - 257) * 256 + threadIdx.x;
        if (idx < 339968) {
            const float* w; int K, t0, local;
            if (idx < 36864)       { w = f1; K = 9;  t0 = 0;  local = idx; }
            else if (idx < 139264) { w = f2; K = 25; t0 = 9;  local = idx - 36864; }
            else                   { w = f3; K = 49; t0 = 34; local = idx - 139264; }
            int k  = local % K;
            int c  = (local / K) & 63;
            int co = local / (K * 64);
            float v = w[local];
            __nv_bfloat16 h = __float2bfloat16(v);
            float hf = __bfloat162float(h);
            __nv_bfloat16 l = __float2bfloat16(v - hf);
            int boff = co * 128 + ((2 * c) ^ ((co & 7) << 4));
            int ui = (t0 + k) * 4096 + (boff >> 1);
            g_whimg[ui] = __bfloat16_as_ushort(h);
            g_wlimg[ui] = __bfloat16_as_ushort(l);
        }
    }
}

// ---------------- mma helpers (target-portable: sm_80 features) -------------
#define LDSM4(r, a) \
    asm volatile("ldmatrix.sync.aligned.m8n8.x4.shared.b16 {%0,%1,%2,%3}, [%4];" \
        : "=r"((r)[0]), "=r"((r)[1]), "=r"((r)[2]), "=r"((r)[3]) : "r"(a))

#define MMA16(d, a, b0, b1) \
    asm volatile("mma.sync.aligned.m16n8k16.row.col.f32.bf16.bf16.f32 " \
        "{%0,%1,%2,%3},{%4,%5,%6,%7},{%8,%9},{%0,%1,%2,%3};" \
        : "+f"((d)[0]), "+f"((d)[1]), "+f"((d)[2]), "+f"((d)[3]) \
        : "r"((a)[0]), "r"((a)[1]), "r"((a)[2]), "r"((a)[3]), "r"(b0), "r"(b1))

#define CPA16(dst, src) \
    asm volatile("cp.async.ca.shared.global [%0], [%1], 16;" :: "r"(dst), "l"(src))

__device__ __forceinline__ u32 smem_u32(const void* p) {
    u32 a;
    asm("{ .reg .u64 t; cvta.to.shared.u64 t, %1; cvt.u32.u64 %0, t; }" : "=r"(a) : "l"(p));
    return a;
}

struct Bil { float w00, w01, w10, w11; u32 pk0, pk1; };

// ---------------------------------------------------------------------------
// Persistent DCNv2 (R8 config): 128 thr, warp tile 32px x 64co, S single-buffer,
// W double-buffer, offset prefetch. Gather loop software-pipelined by 1 iter.
// ---------------------------------------------------------------------------
#define N_ITEMS 896
#define SHOF 0
#define SLOF 16384
#define WBASE 32768
#define CTRL 65536
#define SMEM_BYTES 65664

__global__ void __launch_bounds__(128, 3)
dcn_kernel(const float* __restrict__ off1, const float* __restrict__ m1,
           const float* __restrict__ off2, const float* __restrict__ m2,
           const float* __restrict__ off3, const float* __restrict__ m3,
           float* __restrict__ out)
{
    extern __shared__ char smem[];
    const u32 sb = smem_u32(smem);
    const int tid  = threadIdx.x;
    const int lane = tid & 31;
    const int wid  = tid >> 5;
    int* s_item = (int*)(smem + CTRL);
    int* s_last = (int*)(smem + CTRL + 4);

    const int hw_id = tid >> 4, m = tid & 15;
    const int rowA  = lane & 15;
    const int acol0 = (lane >> 4) << 4;
    const int aswz  = (rowA & 7) << 4;
    const int rbA0  = (32 * wid + rowA) * 128;
    const int rbA1  = rbA0 + 16 * 128;
    const int rowB  = (lane & 7) + ((lane & 16) >> 1);
    const int bcol0 = (lane & 8) << 1;
    const int bswz  = (rowB & 7) << 4;
    const int rbB   = rowB * 128;
    const int r4 = lane >> 2, c2 = 2 * (lane & 3);

    for (;;) {
        __syncthreads();
        if (tid == 0) *s_item = atomicAdd(&g_q, 1);
        __syncthreads();
        int item = *s_item;
        if (item >= N_ITEMS) return;

        int K, kw, pad, co0, wt0, chunk, k0, klen, seg, nsegs, cidx;
        const float *off, *msk;
        float* pbase = 0;
        if (item < 512) {
            chunk = item >> 2; seg = item & 3;
            K = 49; kw = 7; pad = 3; co0 = 128; wt0 = 34;
            k0 = (seg == 0) ? 0 : (13 + 12 * (seg - 1));
            klen = (seg == 0) ? 13 : 12;
            nsegs = 4; cidx = chunk;
            off = off3; msk = m3;
            pbase = g_p3 + ((size_t)(seg * 128 + chunk)) * (64 * 128);
        } else if (item < 768) {
            int it = item - 512;
            chunk = it >> 1; seg = it & 1;
            K = 25; kw = 5; pad = 2; co0 = 64; wt0 = 9;
            k0 = (seg == 0) ? 0 : 13;
            klen = (seg == 0) ? 13 : 12;
            nsegs = 2; cidx = 128 + chunk;
            off = off2; msk = m2;
            pbase = g_p2 + ((size_t)(seg * 128 + chunk)) * (64 * 128);
        } else {
            chunk = item - 768; seg = 0;
            K = 9; kw = 3; pad = 1; co0 = 0; wt0 = 0;
            k0 = 0; klen = 9; nsegs = 1; cidx = 0;
            off = off1; msk = m1;
        }

        const int chunkPx0 = chunk << 7;
        const int b = chunkPx0 >> 12;
        const float* xtB = g_xt + (size_t)b * (64 * 64 * 64);
        const int pixl = (chunkPx0 + hw_id * 16 + m) & 4095;
        const int xo_own = pixl & 63, yo_own = pixl >> 6;
        const float* offB = off + (size_t)b * 2 * K * HW;
        const float* mskB = msk + (size_t)b * K * HW;

        float acc[2][8][4];
#pragma unroll
        for (int i = 0; i < 2; ++i)
#pragma unroll
            for (int j = 0; j < 8; ++j)
#pragma unroll
                for (int q = 0; q < 4; ++q) acc[i][j][q] = 0.f;

        // ---- prologue: prefetch tap k0 offsets + W(k0) -> buf0 ----
        float pf_dy, pf_dx, pf_mm;
        {
            const float* offY = offB + (size_t)(2 * k0) * HW;
            pf_dy = __ldg(offY + pixl);
            pf_dx = __ldg(offY + HW + pixl);
            pf_mm = __ldg(mskB + (size_t)k0 * HW + pixl);

            const char* srcH = (const char*)(g_whimg + (size_t)(wt0 + k0) * 4096) + tid * 16;
            const char* srcL = (const char*)(g_wlimg + (size_t)(wt0 + k0) * 4096) + tid * 16;
            u32 dH = sb + WBASE + tid * 16;
#pragma unroll
            for (int i = 0; i < 4; ++i) {
                CPA16(dH + i * 2048,        srcH + i * 2048);
                CPA16(dH + 8192 + i * 2048, srcL + i * 2048);
            }
            asm volatile("cp.async.commit_group;");
        }

        for (int t = 0; t < klen; ++t) {
            const int k = k0 + t;
            const bool more = (t + 1 < klen);
            __syncthreads();   // all warps done with GEMM(t-1): S reusable

            // ---- Bil for tap t from prefetched regs (pure ALU) ----
            Bil bl;
            {
                const int ky = k / kw, kx = k - ky * kw;
                float py  = (float)(yo_own - pad + ky) + pf_dy;
                float pxx = (float)(xo_own - pad + kx) + pf_dx;
                float mm  = pf_mm;
                float fy = floorf(py), fx = floorf(pxx);
                float wy = py - fy,    wx = pxx - fx;
                int y0 = (int)fy, x0 = (int)fx;
                int y1 = y0 + 1,  x1 = x0 + 1;
                float vy0 = (y0 >= 0 && y0 < 64) ? 1.f : 0.f;
                float vy1 = (y1 >= 0 && y1 < 64) ? 1.f : 0.f;
                float vx0 = (x0 >= 0 && x0 < 64) ? 1.f : 0.f;
                float vx1 = (x1 >= 0 && x1 < 64) ? 1.f : 0.f;
                bl.w00 = (1.f - wy) * (1.f - wx) * mm * vy0 * vx0;
                bl.w01 = (1.f - wy) * wx         * mm * vy0 * vx1;
                bl.w10 = wy         * (1.f - wx) * mm * vy1 * vx0;
                bl.w11 = wy         * wx         * mm * vy1 * vx1;
                int cy0 = min(max(y0, 0), 63), cy1 = min(max(y1, 0), 63);
                int cx0 = min(max(x0, 0), 63), cx1 = min(max(x1, 0), 63);
                bl.pk0 = ((u32)(cy0 * 64 + cx0) << 16) | (u32)(cy0 * 64 + cx1);
                bl.pk1 = ((u32)(cy1 * 64 + cx0) << 16) | (u32)(cy1 * 64 + cx1);
            }

            // ---- prefetch offsets for tap t+1 (latency hidden behind gather) ----
            if (more) {
                const float* offY = offB + (size_t)(2 * (k + 1)) * HW;
                pf_dy = __ldg(offY + pixl);
                pf_dx = __ldg(offY + HW + pixl);
                pf_mm = __ldg(mskB + (size_t)(k + 1) * HW + pixl);
            }

            // ---- gather tap t -> S (bf16 hi/lo), pipelined by 1 iteration ----
            {
                const float4* vp = (const float4*)xtB;
                const int sbase = lane & 16;

                float W00c, W01c, W10c, W11c;
                float4 v00c, v01c, v10c, v11c;
                {   // prime iteration 0
                    int src = sbase;
                    W00c = __shfl_sync(0xffffffffu, bl.w00, src);
                    W01c = __shfl_sync(0xffffffffu, bl.w01, src);
                    W10c = __shfl_sync(0xffffffffu, bl.w10, src);
                    W11c = __shfl_sync(0xffffffffu, bl.w11, src);
                    u32 P0 = __shfl_sync(0xffffffffu, bl.pk0, src);
                    u32 P1 = __shfl_sync(0xffffffffu, bl.pk1, src);
                    v00c = vp[(P0 >> 16) * 16 + m];
                    v01c = vp[(P0 & 0xffffu) * 16 + m];
                    v10c = vp[(P1 >> 16) * 16 + m];
                    v11c = vp[(P1 & 0xffffu) * 16 + m];
                }
#pragma unroll
                for (int it = 0; it < 16; ++it) {
                    float W00n, W01n, W10n, W11n;
                    float4 v00n, v01n, v10n, v11n;
                    if (it < 15) {   // issue next iteration's loads early
                        int src = sbase + it + 1;
                        W00n = __shfl_sync(0xffffffffu, bl.w00, src);
                        W01n = __shfl_sync(0xffffffffu, bl.w01, src);
                        W10n = __shfl_sync(0xffffffffu, bl.w10, src);
                        W11n = __shfl_sync(0xffffffffu, bl.w11, src);
                        u32 P0 = __shfl_sync(0xffffffffu, bl.pk0, src);
                        u32 P1 = __shfl_sync(0xffffffffu, bl.pk1, src);
                        v00n = vp[(P0 >> 16) * 16 + m];
                        v01n = vp[(P0 & 0xffffu) * 16 + m];
                        v10n = vp[(P1 >> 16) * 16 + m];
                        v11n = vp[(P1 & 0xffffu) * 16 + m];
                    }

                    float s0 = fmaf(W00c, v00c.x, fmaf(W01c, v01c.x, fmaf(W10c, v10c.x, W11c * v11c.x)));
                    float s1 = fmaf(W00c, v00c.y, fmaf(W01c, v01c.y, fmaf(W10c, v10c.y, W11c * v11c.y)));
                    float s2 = fmaf(W00c, v00c.z, fmaf(W01c, v01c.z, fmaf(W10c, v10c.z, W11c * v11c.z)));
                    float s3 = fmaf(W00c, v00c.w, fmaf(W01c, v01c.w, fmaf(W10c, v10c.w, W11c * v11c.w)));

                    __nv_bfloat162 h01 = __floats2bfloat162_rn(s0, s1);
                    __nv_bfloat162 h23 = __floats2bfloat162_rn(s2, s3);
                    float2 f01 = __bfloat1622float2(h01);
                    float2 f23 = __bfloat1622float2(h23);
                    __nv_bfloat162 l01 = __floats2bfloat162_rn(s0 - f01.x, s1 - f01.y);
                    __nv_bfloat162 l23 = __floats2bfloat162_rn(s2 - f23.x, s3 - f23.y);

                    int px = hw_id * 16 + it;
                    int cb = px * 128 + ((8 * m) ^ ((px & 7) << 4));
                    *(uint2*)(smem + SHOF + cb) = make_uint2(*(u32*)&h01, *(u32*)&h23);
                    *(uint2*)(smem + SLOF + cb) = make_uint2(*(u32*)&l01, *(u32*)&l23);

                    if (it < 15) {
                        W00c = W00n; W01c = W01n; W10c = W10n; W11c = W11n;
                        v00c = v00n; v01c = v01n; v10c = v10n; v11c = v11n;
                    }
                }
            }
            asm volatile("cp.async.wait_group 0;");   // W(t) resident
            __syncthreads();                          // S + W visible

            // ---- issue W(t+1) copy into the other buffer (overlaps GEMM) ----
            if (more) {
                const char* srcH = (const char*)(g_whimg + (size_t)(wt0 + k + 1) * 4096) + tid * 16;
                const char* srcL = (const char*)(g_wlimg + (size_t)(wt0 + k + 1) * 4096) + tid * 16;
                u32 dH = sb + WBASE + (u32)((t + 1) & 1) * 16384 + tid * 16;
#pragma unroll
                for (int i = 0; i < 4; ++i) {
                    CPA16(dH + i * 2048,        srcH + i * 2048);
                    CPA16(dH + 8192 + i * 2048, srcL + i * 2048);
                }
                asm volatile("cp.async.commit_group;");
            }

            // ---- GEMM(t): 3-pass bf16 split, fp32 accum ----
            const u32 wofs = WBASE + (u32)(t & 1) * 16384;
#pragma unroll
            for (int k4 = 0; k4 < 4; ++k4) {
                u32 colA = (u32)((32 * k4 + acol0) ^ aswz);
                u32 aH0[4], aH1[4], aL0[4], aL1[4];
                LDSM4(aH0, sb + SHOF + rbA0 + colA);
                LDSM4(aH1, sb + SHOF + rbA1 + colA);
                LDSM4(aL0, sb + SLOF + rbA0 + colA);
                LDSM4(aL1, sb + SLOF + rbA1 + colA);
                u32 colB = (u32)((32 * k4 + bcol0) ^ bswz);
#pragma unroll
                for (int p = 0; p < 4; ++p) {
                    u32 badr = (u32)(rbB + p * 2048) + colB;
                    u32 bH[4], bL[4];
                    LDSM4(bH, sb + wofs + badr);
                    LDSM4(bL, sb + wofs + 8192 + badr);
                    MMA16(acc[0][2 * p],     aH0, bH[0], bH[1]);
                    MMA16(acc[1][2 * p],     aH1, bH[0], bH[1]);
                    MMA16(acc[0][2 * p + 1], aH0, bH[2], bH[3]);
                    MMA16(acc[1][2 * p + 1], aH1, bH[2], bH[3]);
                    MMA16(acc[0][2 * p],     aL0, bH[0], bH[1]);
                    MMA16(acc[1][2 * p],     aL1, bH[0], bH[1]);
                    MMA16(acc[0][2 * p + 1], aL0, bH[2], bH[3]);
                    MMA16(acc[1][2 * p + 1], aL1, bH[2], bH[3]);
                    MMA16(acc[0][2 * p],     aH0, bL[0], bL[1]);
                    MMA16(acc[1][2 * p],     aH1, bL[0], bL[1]);
                    MMA16(acc[0][2 * p + 1], aH0, bL[2], bL[3]);
                    MMA16(acc[1][2 * p + 1], aH1, bL[2], bL[3]);
                }
            }
        }

        // ---------------- epilogue ----------------
        if (nsegs == 1) {
            float* ob = out + (size_t)(b * 192 + co0) * HW;
#pragma unroll
            for (int mt = 0; mt < 2; ++mt) {
                int pxl = 32 * wid + 16 * mt + r4;
                int pix0 = (chunkPx0 + pxl) & 4095;
                int pix1 = (chunkPx0 + pxl + 8) & 4095;
#pragma unroll
                for (int nt = 0; nt < 8; ++nt) {
                    int co = 8 * nt + c2;
                    ob[(size_t)co * HW + pix0]       = acc[mt][nt][0];
                    ob[(size_t)(co + 1) * HW + pix0] = acc[mt][nt][1];
                    ob[(size_t)co * HW + pix1]       = acc[mt][nt][2];
                    ob[(size_t)(co + 1) * HW + pix1] = acc[mt][nt][3];
                }
            }
        } else {
#pragma unroll
            for (int mt = 0; mt < 2; ++mt) {
                int pxl = 32 * wid + 16 * mt + r4;
#pragma unroll
                for (int nt = 0; nt < 8; ++nt) {
                    int co = 8 * nt + c2;
                    pbase[co * 128 + pxl]           = acc[mt][nt][0];
                    pbase[(co + 1) * 128 + pxl]     = acc[mt][nt][1];
                    pbase[co * 128 + pxl + 8]       = acc[mt][nt][2];
                    pbase[(co + 1) * 128 + pxl + 8] = acc[mt][nt][3];
                }
            }
            __threadfence();
            __syncthreads();
            if (tid == 0)
                *s_last = (atomicAdd(&g_cnt[cidx], 1) == nsegs - 1) ? 1 : 0;
            __syncthreads();
            if (*s_last) {
                const float* basep = (nsegs == 4) ? g_p3 : g_p2;
                float* outB = out + (size_t)(b * 192 + co0) * HW + ((chunkPx0 + tid) & 4095);
                for (int co = 0; co < 64; ++co) {
                    float s = 0.f;
                    for (int sg = 0; sg < nsegs; ++sg)
                        s += basep[((size_t)(sg * 128 + chunk) * 64 + co) * 128 + tid];
                    outB[(size_t)co * HW] = s;
                }
            }
        }
    }
}

extern "C" void kernel_launch(void* const* d_in, const int* in_sizes, int n_in,
                              void* d_out, int out_size) {
    const float* x  = (const float*)d_in[0];
    const float* f1 = (const float*)d_in[1];
    const float* o1 = (const float*)d_in[2];
    const float* m1 = (const float*)d_in[3];
    const float* f2 = (const float*)d_in[4];
    const float* o2 = (const float*)d_in[5];
    const float* m2 = (const float*)d_in[6];
    const float* f3 = (const float*)d_in[7];
    const float* o3 = (const float*)d_in[8];
    const float* m3 = (const float*)d_in[9];
    float* out = (float*)d_out;

    cudaFuncSetAttribute(dcn_kernel, cudaFuncAttributeMaxDynamicSharedMemorySize, SMEM_BYTES);
    prep_kernel<<<1585, 256>>>(x, f1, f2, f3);
    dcn_kernel<<<444, 128, SMEM_BYTES>>>(o1, m1, o2, m2, o3, m3, out);
}